// round 5
// baseline (speedup 1.0000x reference)
#include <cuda_runtime.h>
#include <cstdint>
#include <math_constants.h>

// B=64, I=1024, O=1024, et in {0,1,2}
// tnorm (op==0): val = (et==2 ? 1-x : x) + (et==0 ? +10 : 0), reduce = min
// tconorm:       same with -10, reduce = max
// Sign trick: s = tnorm ? +1 : -1.  w = s*v = (et==2 ? s - s*x : s*x) + (et==0 ? 10 : 0)
//   answer = s * min(w)   (exact; s*offset = +10 in both cases)

#define B_DIM 64
#define I_DIM 1024
#define O_DIM 1024
#define THREADS 256
#define NBLOCKS 592                      // 4 per SM on 148 SMs
#define N_TILES 4096                     // 64 b * 64 groups; tile = 16 rows
#define ROWS_PER_TILE 16                 // 8 warps * 2 rows
#define FULL_TILE_BLOCKS (N_TILES - 6 * NBLOCKS)   // 544 blocks get 7 tiles

static __device__ __forceinline__
float half_row_min(const int4* __restrict__ e, const float4* __restrict__ xs4,
                   int lane, float s)
{
    float red = CUDART_INF_F;
    #pragma unroll
    for (int j = 0; j < 4; ++j) {
        const float4 xv = xs4[j * 32 + lane];
        float t0 = s * xv.x, t1 = s * xv.y, t2 = s * xv.z, t3 = s * xv.w;
        float v0 = (e[j].x == 2) ? (s - t0) : t0;
        float v1 = (e[j].y == 2) ? (s - t1) : t1;
        float v2 = (e[j].z == 2) ? (s - t2) : t2;
        float v3 = (e[j].w == 2) ? (s - t3) : t3;
        if (e[j].x == 0) v0 += 10.0f;
        if (e[j].y == 0) v1 += 10.0f;
        if (e[j].z == 0) v2 += 10.0f;
        if (e[j].w == 0) v3 += 10.0f;
        red = fminf(red, fminf(fminf(v0, v1), fminf(v2, v3)));
    }
    return red;
}

static __device__ __forceinline__
float warp_min(float red)
{
    #pragma unroll
    for (int sh = 16; sh > 0; sh >>= 1)
        red = fminf(red, __shfl_xor_sync(0xffffffffu, red, sh));
    return red;
}

__global__ void __launch_bounds__(THREADS, 4)
ffcl_kernel(const float* __restrict__ x,
            const int4* __restrict__ et4,
            const int* __restrict__ op_idx,
            float* __restrict__ out)
{
    __shared__ float xs[2][I_DIM];       // double-buffered x row (8 KB)

    const int k    = blockIdx.x;
    const int warp = threadIdx.x >> 5;
    const int lane = threadIdx.x & 31;
    const int ntiles = 6 + (k < FULL_TILE_BLOCKS ? 1 : 0);

    // ---- Prologue: stage x for tile 0, issue its first half-batch ----
    {
        const int b0 = k >> 6;
        reinterpret_cast<float4*>(xs[0])[threadIdx.x] =
            reinterpret_cast<const float4*>(x + (size_t)b0 * I_DIM)[threadIdx.x];
    }

    int4 A[4], Bv[4];
    {
        const int b0 = k >> 6, g0 = k & 63;
        const int o00 = g0 * ROWS_PER_TILE + warp * 2;
        const int4* rowp = et4 + (size_t)(b0 * O_DIM + o00) * (I_DIM / 4);
        #pragma unroll
        for (int j = 0; j < 4; ++j)
            A[j] = __ldcs(rowp + j * 32 + lane);
    }
    __syncthreads();

    int buf = 0;
    for (int i = 0; i < ntiles; ++i) {
        const int t = k + i * NBLOCKS;
        const int b = t >> 6;
        const int g = t & 63;
        const int o0 = g * ROWS_PER_TILE + warp * 2;
        const bool more = (i + 1 < ntiles);
        const int tn = t + NBLOCKS;               // next tile (valid iff more)

        // Prefetch next tile's x row into registers (overlaps tile compute).
        float4 xn = make_float4(0.f, 0.f, 0.f, 0.f);
        if (more)
            xn = reinterpret_cast<const float4*>(x + (size_t)(tn >> 6) * I_DIM)[threadIdx.x];

        const float s0 = (op_idx[o0]     == 0) ? 1.0f : -1.0f;
        const float s1 = (op_idx[o0 + 1] == 0) ? 1.0f : -1.0f;

        const int4*   rowp = et4 + (size_t)(b * O_DIM + o0) * (I_DIM / 4);
        const float4* xs4  = reinterpret_cast<const float4*>(xs[buf]);

        // --- Row 0 ---
        #pragma unroll
        for (int j = 0; j < 4; ++j)               // H1: row0 second half
            Bv[j] = __ldcs(rowp + 128 + j * 32 + lane);

        float red0 = half_row_min(A, xs4, lane, s0);

        #pragma unroll
        for (int j = 0; j < 4; ++j)               // H2: row1 first half
            A[j] = __ldcs(rowp + 256 + j * 32 + lane);

        red0 = fminf(red0, half_row_min(Bv, xs4 + 128, lane, s0));
        red0 = warp_min(red0);
        if (lane == 0)
            out[(size_t)b * O_DIM + o0] = s0 * red0;

        // --- Row 1 ---
        #pragma unroll
        for (int j = 0; j < 4; ++j)               // H3: row1 second half
            Bv[j] = __ldcs(rowp + 384 + j * 32 + lane);

        float red1 = half_row_min(A, xs4, lane, s1);

        if (more) {                                // H0 of NEXT tile
            const int gn = tn & 63;
            const int on = gn * ROWS_PER_TILE + warp * 2;
            const int4* rown = et4 + (size_t)((tn >> 6) * O_DIM + on) * (I_DIM / 4);
            #pragma unroll
            for (int j = 0; j < 4; ++j)
                A[j] = __ldcs(rown + j * 32 + lane);
        }

        red1 = fminf(red1, half_row_min(Bv, xs4 + 128, lane, s1));
        red1 = warp_min(red1);
        if (lane == 0)
            out[(size_t)b * O_DIM + o0 + 1] = s1 * red1;

        // Stage next tile's x; one barrier per tile protects both buffers.
        if (more)
            reinterpret_cast<float4*>(xs[buf ^ 1])[threadIdx.x] = xn;
        __syncthreads();
        buf ^= 1;
    }
}

extern "C" void kernel_launch(void* const* d_in, const int* in_sizes, int n_in,
                              void* d_out, int out_size)
{
    (void)in_sizes; (void)n_in; (void)out_size;
    const float* x      = (const float*)d_in[0];
    const int4*  et4    = (const int4*)d_in[1];
    const int*   op_idx = (const int*)d_in[2];
    float*       out    = (float*)d_out;

    ffcl_kernel<<<NBLOCKS, THREADS>>>(x, et4, op_idx, out);
}

// round 6
// speedup vs baseline: 1.0522x; 1.0522x over previous
#include <cuda_runtime.h>
#include <cstdint>
#include <math_constants.h>

// B=64, I=1024, O=1024, et in {0,1,2}
// tnorm (op==0): val = (et==2 ? 1-x : x) + (et==0 ? +10 : 0), reduce = min
// tconorm:       same with -10, reduce = max
// Sign trick: s = tnorm ? +1 : -1.  w = s*v = (et==2 ? s - s*x : s*x) + (et==0 ? 10 : 0)
//   answer = s * min(w)   (exact; s*offset = +10 in both cases)

#define B_DIM 64
#define I_DIM 1024
#define O_DIM 1024
#define THREADS 256
#define ROWS_PER_TILE 16                 // 8 warps * 2 rows
#define GROUPS_PER_B (O_DIM / ROWS_PER_TILE)   // 64

static __device__ __forceinline__
float half_row_min(const int4* __restrict__ e, const float4* __restrict__ xs4,
                   int lane, float s)
{
    float red = CUDART_INF_F;
    #pragma unroll
    for (int j = 0; j < 4; ++j) {
        const float4 xv = xs4[j * 32 + lane];
        float t0 = s * xv.x, t1 = s * xv.y, t2 = s * xv.z, t3 = s * xv.w;
        float v0 = (e[j].x == 2) ? (s - t0) : t0;
        float v1 = (e[j].y == 2) ? (s - t1) : t1;
        float v2 = (e[j].z == 2) ? (s - t2) : t2;
        float v3 = (e[j].w == 2) ? (s - t3) : t3;
        if (e[j].x == 0) v0 += 10.0f;
        if (e[j].y == 0) v1 += 10.0f;
        if (e[j].z == 0) v2 += 10.0f;
        if (e[j].w == 0) v3 += 10.0f;
        red = fminf(red, fminf(fminf(v0, v1), fminf(v2, v3)));
    }
    return red;
}

static __device__ __forceinline__
float warp_min(float red)
{
    #pragma unroll
    for (int sh = 16; sh > 0; sh >>= 1)
        red = fminf(red, __shfl_xor_sync(0xffffffffu, red, sh));
    return red;
}

__global__ void __launch_bounds__(THREADS, 3)
ffcl_kernel(const float* __restrict__ x,
            const int4* __restrict__ et4,
            const int* __restrict__ op_idx,
            float* __restrict__ out)
{
    __shared__ float xs[I_DIM];

    const int b = blockIdx.x >> 6;              // / GROUPS_PER_B
    const int g = blockIdx.x & (GROUPS_PER_B - 1);

    const int warp = threadIdx.x >> 5;
    const int lane = threadIdx.x & 31;
    const int o0   = g * ROWS_PER_TILE + warp * 2;

    const int4* rowp = et4 + (size_t)(b * O_DIM + o0) * (I_DIM / 4);

    // ---- Prologue: et loads FIRST (stream starts immediately), then x stage.
    int4 A[4], Bv[4], C[4];
    #pragma unroll
    for (int j = 0; j < 4; ++j)                  // H0: row0 first half
        A[j] = __ldcs(rowp + j * 32 + lane);
    #pragma unroll
    for (int j = 0; j < 4; ++j)                  // H1: row0 second half
        Bv[j] = __ldcs(rowp + 128 + j * 32 + lane);

    const float s0 = (op_idx[o0]     == 0) ? 1.0f : -1.0f;
    const float s1 = (op_idx[o0 + 1] == 0) ? 1.0f : -1.0f;

    // Stage x[b,:] into shared (4 KB), one float4 per thread; overlaps the
    // in-flight et loads above.
    reinterpret_cast<float4*>(xs)[threadIdx.x] =
        reinterpret_cast<const float4*>(x + (size_t)b * I_DIM)[threadIdx.x];
    __syncthreads();

    const float4* xs4 = reinterpret_cast<const float4*>(xs);

    // ---- Steady state: depth-2 pipeline (8 LDG.128 in flight per warp).
    #pragma unroll
    for (int j = 0; j < 4; ++j)                  // H2: row1 first half
        C[j] = __ldcs(rowp + 256 + j * 32 + lane);

    float red0 = half_row_min(A, xs4, lane, s0);

    #pragma unroll
    for (int j = 0; j < 4; ++j)                  // H3: row1 second half
        A[j] = __ldcs(rowp + 384 + j * 32 + lane);

    red0 = fminf(red0, half_row_min(Bv, xs4 + 128, lane, s0));
    red0 = warp_min(red0);
    if (lane == 0)
        out[(size_t)b * O_DIM + o0] = s0 * red0;

    float red1 = half_row_min(C, xs4, lane, s1);
    red1 = fminf(red1, half_row_min(A, xs4 + 128, lane, s1));
    red1 = warp_min(red1);
    if (lane == 0)
        out[(size_t)b * O_DIM + o0 + 1] = s1 * red1;
}

extern "C" void kernel_launch(void* const* d_in, const int* in_sizes, int n_in,
                              void* d_out, int out_size)
{
    (void)in_sizes; (void)n_in; (void)out_size;
    const float* x      = (const float*)d_in[0];
    const int4*  et4    = (const int4*)d_in[1];
    const int*   op_idx = (const int*)d_in[2];
    float*       out    = (float*)d_out;

    const int blocks = B_DIM * GROUPS_PER_B;    // 4096
    ffcl_kernel<<<blocks, THREADS>>>(x, et4, op_idx, out);
}